// round 3
// baseline (speedup 1.0000x reference)
#include <cuda_runtime.h>
#include <cstdint>

#define NJ 64
#define DD 32
#define HH 64

// Shared memory layout (float offsets)
#define S_WC  0                    // Wm1 rearranged [32][128] = 4096 (G1|G2 combined weights)
#define S_WM2 (S_WC + 4096)        // [64][32] = 2048
#define S_WU1 (S_WM2 + 2048)       // [64][64] = 4096
#define S_WU2 (S_WU1 + 4096)       // [64][32] = 2048
#define S_B   (S_WU2 + 2048)       // bm1[64] bm2[32] bu1[64] bu2[32] = 192
#define S_F   (S_B + 192)          // [64][36] = 2304
#define S_M   (S_F + 2304)         // [64][36] = 2304
#define S_G   (S_M + 2304)         // [64][132] = 8448 ; reused later as U[64][68]
#define S_U   S_G
#define S_TOTAL (S_G + 8448)       // 25536 floats = 102144 bytes

union F2 { uint64_t u; float2 f; };

__device__ __forceinline__ uint64_t ld2s(const float* p) {
    return *reinterpret_cast<const uint64_t*>(p);
}
__device__ __forceinline__ void fma2(uint64_t& d, uint64_t a, uint64_t b) {
    asm("fma.rn.f32x2 %0, %1, %2, %0;" : "+l"(d) : "l"(a), "l"(b));
}
__device__ __forceinline__ uint64_t dup2(float a) {
    uint64_t r; asm("mov.b64 %0, {%1, %1};" : "=l"(r) : "f"(a)); return r;
}
__device__ __forceinline__ void relu2(uint64_t& v) {
    F2 x; x.u = v;
    x.f.x = fmaxf(x.f.x, 0.f);
    x.f.y = fmaxf(x.f.y, 0.f);
    v = x.u;
}

extern __shared__ float sm[];

__global__ void __launch_bounds__(256, 2)
agn_kernel(const float* __restrict__ Fg,
           const float* __restrict__ Wm1, const float* __restrict__ bm1,
           const float* __restrict__ Wm2, const float* __restrict__ bm2,
           const float* __restrict__ Wu1, const float* __restrict__ bu1,
           const float* __restrict__ Wu2, const float* __restrict__ bu2,
           const float* __restrict__ rwp,
           float* __restrict__ Og)
{
    const int b = blockIdx.x;
    const int t = threadIdx.x;

    // ---- stage 0: load weights / biases / features into smem ----
    // Wm1 rearranged into Wc[32][128]: Wc[k][c] = Wm1[k][c] (c<64), Wm1[k+32][c-64] (c>=64)
    #pragma unroll
    for (int i = 0; i < 16; i++) {
        int gi = t + i * 256;
        int kg = gi >> 6, h = gi & 63;
        sm[S_WC + (kg & 31) * 128 + (kg >> 5) * 64 + h] = Wm1[gi];
    }
    #pragma unroll
    for (int i = 0; i < 2; i++) {
        int g = t + i * 256;
        reinterpret_cast<float4*>(sm + S_WM2)[g] = reinterpret_cast<const float4*>(Wm2)[g];
    }
    #pragma unroll
    for (int i = 0; i < 4; i++) {
        int g = t + i * 256;
        reinterpret_cast<float4*>(sm + S_WU1)[g] = reinterpret_cast<const float4*>(Wu1)[g];
    }
    #pragma unroll
    for (int i = 0; i < 2; i++) {
        int g = t + i * 256;
        reinterpret_cast<float4*>(sm + S_WU2)[g] = reinterpret_cast<const float4*>(Wu2)[g];
    }
    if (t < 64)        sm[S_B + t]       = bm1[t];
    else if (t < 96)   sm[S_B + t]       = bm2[t - 64];
    else if (t < 160)  sm[S_B + t]       = bu1[t - 96];
    else if (t < 192)  sm[S_B + t]       = bu2[t - 160];

    const float4* Fb4 = reinterpret_cast<const float4*>(Fg + (size_t)b * (NJ * DD));
    #pragma unroll
    for (int i = 0; i < 2; i++) {
        int g = t + i * 256;             // float4 index; 512 total
        int n = g >> 3, d4 = g & 7;      // node, float4-within-row
        *reinterpret_cast<float4*>(sm + S_F + n * 36 + d4 * 4) = Fb4[g];
    }
    __syncthreads();

    // ---- Stage 1: G[64][128] = F[64][32] @ Wc[32][128]  (no bias) ----
    // thread: cb = t&15 -> 8 cols at c0=cb*8 ; p = t>>4 -> nodes {p, p+16, p+32, p+48}
    {
        const int cb = t & 15, p = t >> 4;
        const int c0 = cb * 8;
        uint64_t acc[16];                // [node j][pair q]
        #pragma unroll
        for (int i = 0; i < 16; i++) acc[i] = 0;

        #pragma unroll
        for (int k4 = 0; k4 < 8; k4++) {
            float fa[4][4];
            #pragma unroll
            for (int j = 0; j < 4; j++) {
                float4 v = *reinterpret_cast<const float4*>(sm + S_F + (p + j * 16) * 36 + k4 * 4);
                fa[j][0] = v.x; fa[j][1] = v.y; fa[j][2] = v.z; fa[j][3] = v.w;
            }
            #pragma unroll
            for (int kk = 0; kk < 4; kk++) {
                const ulonglong2* wp =
                    reinterpret_cast<const ulonglong2*>(sm + S_WC + (k4 * 4 + kk) * 128 + c0);
                ulonglong2 wlo = wp[0];
                ulonglong2 whi = wp[1];
                #pragma unroll
                for (int j = 0; j < 4; j++) {
                    uint64_t a2 = dup2(fa[j][kk]);
                    fma2(acc[j * 4 + 0], a2, wlo.x);
                    fma2(acc[j * 4 + 1], a2, wlo.y);
                    fma2(acc[j * 4 + 2], a2, whi.x);
                    fma2(acc[j * 4 + 3], a2, whi.y);
                }
            }
        }
        #pragma unroll
        for (int j = 0; j < 4; j++) {
            float* dst = sm + S_G + (p + j * 16) * 132 + c0;
            *reinterpret_cast<uint64_t*>(dst + 0) = acc[j * 4 + 0];
            *reinterpret_cast<uint64_t*>(dst + 2) = acc[j * 4 + 1];
            *reinterpret_cast<uint64_t*>(dst + 4) = acc[j * 4 + 2];
            *reinterpret_cast<uint64_t*>(dst + 6) = acc[j * 4 + 3];
        }
    }
    __syncthreads();

    // ---- Stage 2: per-edge message MLP (h1 streamed) + two-phase scatter ----
    // 2 threads/edge: e = t>>1, d0 = (t&1)*16. Edge e<63: dst=e,src=e+1 ; else dst=e-62,src=e-63.
    {
        uint64_t macc[8];
        const int e = t >> 1;
        const int d0 = (t & 1) * 16;
        int dn = 0;
        if (t < 252) {
            int sn;
            if (e < 63) { dn = e;      sn = e + 1; }
            else        { dn = e - 62; sn = e - 63; }
            #pragma unroll
            for (int q = 0; q < 8; q++) macc[q] = ld2s(sm + S_B + 64 + d0 + 2 * q);

            const float* g1p = sm + S_G + dn * 132;       // G1 half
            const float* g2p = sm + S_G + sn * 132 + 64;  // G2 half
            #pragma unroll
            for (int k4 = 0; k4 < 16; k4++) {
                float4 g1 = *reinterpret_cast<const float4*>(g1p + k4 * 4);
                float4 g2 = *reinterpret_cast<const float4*>(g2p + k4 * 4);
                float4 bb = *reinterpret_cast<const float4*>(sm + S_B + k4 * 4);
                float h[4];
                h[0] = fmaxf(g1.x + g2.x + bb.x, 0.f);
                h[1] = fmaxf(g1.y + g2.y + bb.y, 0.f);
                h[2] = fmaxf(g1.z + g2.z + bb.z, 0.f);
                h[3] = fmaxf(g1.w + g2.w + bb.w, 0.f);
                #pragma unroll
                for (int kk = 0; kk < 4; kk++) {
                    const ulonglong2* wp =
                        reinterpret_cast<const ulonglong2*>(sm + S_WM2 + (k4 * 4 + kk) * 32 + d0);
                    ulonglong2 wlo = wp[0];
                    ulonglong2 whi = wp[1];
                    uint64_t a2 = dup2(h[kk]);
                    fma2(macc[0], a2, wlo.x);
                    fma2(macc[1], a2, wlo.y);
                    fma2(macc[2], a2, whi.x);
                    fma2(macc[3], a2, whi.y);
                }
            }
            #pragma unroll
            for (int q = 0; q < 4; q++) relu2(macc[q]);
            // also handle second 8 cols? d0 selects 16 cols -> 8 pairs; loop covered only 4.
        }
        // NOTE: the block above covers pairs 0..3 (8 cols); cover pairs 4..7 below.
        if (t < 252) {
            const int sn2 = (e < 63) ? e + 1 : e - 63;
            const float* g1p = sm + S_G + dn * 132;
            const float* g2p = sm + S_G + sn2 * 132 + 64;
            #pragma unroll
            for (int k4 = 0; k4 < 16; k4++) {
                float4 g1 = *reinterpret_cast<const float4*>(g1p + k4 * 4);
                float4 g2 = *reinterpret_cast<const float4*>(g2p + k4 * 4);
                float4 bb = *reinterpret_cast<const float4*>(sm + S_B + k4 * 4);
                float h[4];
                h[0] = fmaxf(g1.x + g2.x + bb.x, 0.f);
                h[1] = fmaxf(g1.y + g2.y + bb.y, 0.f);
                h[2] = fmaxf(g1.z + g2.z + bb.z, 0.f);
                h[3] = fmaxf(g1.w + g2.w + bb.w, 0.f);
                #pragma unroll
                for (int kk = 0; kk < 4; kk++) {
                    const ulonglong2* wp =
                        reinterpret_cast<const ulonglong2*>(sm + S_WM2 + (k4 * 4 + kk) * 32 + d0 + 8);
                    ulonglong2 wlo = wp[0];
                    ulonglong2 whi = wp[1];
                    uint64_t a2 = dup2(h[kk]);
                    fma2(macc[4], a2, wlo.x);
                    fma2(macc[5], a2, wlo.y);
                    fma2(macc[6], a2, whi.x);
                    fma2(macc[7], a2, whi.y);
                }
            }
            #pragma unroll
            for (int q = 4; q < 8; q++) relu2(macc[q]);
        }
        // phase A: forward edges (dst = e, e<63) store; spare threads zero node 63 row
        if (t < 126) {
            float* m = sm + S_M + e * 36 + d0;
            #pragma unroll
            for (int q = 0; q < 8; q++) {
                // pairs 0..3 -> cols d0+0..7 ; pairs 4..7 -> cols d0+8..15
                *reinterpret_cast<uint64_t*>(m + 2 * q) = macc[q];
            }
        } else if (t >= 252) {
            int j0 = (t - 252) * 8;
            #pragma unroll
            for (int j = 0; j < 8; j++) sm[S_M + 63 * 36 + j0 + j] = 0.f;
        }
        __syncthreads();
        // phase B: backward edges (dst = e-62) accumulate
        if (t >= 126 && t < 252) {
            float* m = sm + S_M + dn * 36 + d0;
            #pragma unroll
            for (int q = 0; q < 8; q++) {
                F2 x; x.u = macc[q];
                m[2 * q + 0] += x.f.x;
                m[2 * q + 1] += x.f.y;
            }
        }
        __syncthreads();
    }

    // ---- Stage 3: U[64][64] = relu([F | M] @ Wu1 + bu1), U stored over G ----
    // thread: cb = t&7 -> 8 cols c0=cb*8 ; p = t>>3 -> nodes {p, p+32}
    {
        const int cb = t & 7, p = t >> 3;
        const int c0 = cb * 8;
        uint64_t acc[8];   // [node 0/1][pair 0..3]
        #pragma unroll
        for (int q = 0; q < 4; q++) {
            uint64_t bv = ld2s(sm + S_B + 96 + c0 + 2 * q);
            acc[q] = bv;
            acc[4 + q] = bv;
        }
        // half 1: A = F, W rows 0..31 ; half 2: A = M, W rows 32..63
        #pragma unroll
        for (int half = 0; half < 2; half++) {
            const float* A = sm + (half == 0 ? S_F : S_M);
            const int kbase = half * 32;
            #pragma unroll
            for (int k4 = 0; k4 < 8; k4++) {
                float4 v0 = *reinterpret_cast<const float4*>(A + p * 36 + k4 * 4);
                float4 v1 = *reinterpret_cast<const float4*>(A + (p + 32) * 36 + k4 * 4);
                float a0[4] = {v0.x, v0.y, v0.z, v0.w};
                float a1[4] = {v1.x, v1.y, v1.z, v1.w};
                #pragma unroll
                for (int kk = 0; kk < 4; kk++) {
                    const ulonglong2* wp = reinterpret_cast<const ulonglong2*>(
                        sm + S_WU1 + (kbase + k4 * 4 + kk) * 64 + c0);
                    ulonglong2 wlo = wp[0];
                    ulonglong2 whi = wp[1];
                    uint64_t x0 = dup2(a0[kk]);
                    uint64_t x1 = dup2(a1[kk]);
                    fma2(acc[0], x0, wlo.x);
                    fma2(acc[1], x0, wlo.y);
                    fma2(acc[2], x0, whi.x);
                    fma2(acc[3], x0, whi.y);
                    fma2(acc[4], x1, wlo.x);
                    fma2(acc[5], x1, wlo.y);
                    fma2(acc[6], x1, whi.x);
                    fma2(acc[7], x1, whi.y);
                }
            }
        }
        __syncthreads();   // G fully consumed by stage 2 before overwrite as U
        float* u0 = sm + S_U + p * 68 + c0;
        float* u1 = sm + S_U + (p + 32) * 68 + c0;
        #pragma unroll
        for (int q = 0; q < 4; q++) {
            relu2(acc[q]);
            relu2(acc[4 + q]);
            *reinterpret_cast<uint64_t*>(u0 + 2 * q) = acc[q];
            *reinterpret_cast<uint64_t*>(u1 + 2 * q) = acc[4 + q];
        }
    }
    __syncthreads();

    // ---- Stage 4: out = rw*(U @ Wu2 + bu2) + (1-rw)*F ----
    // thread: cb = t&7 -> 4 cols c0=cb*4 ; p = t>>3 -> nodes {p, p+32}
    {
        const int cb = t & 7, p = t >> 3;
        const int c0 = cb * 4;
        uint64_t acc[4];   // [node][pair]
        #pragma unroll
        for (int q = 0; q < 2; q++) {
            uint64_t bv = ld2s(sm + S_B + 160 + c0 + 2 * q);
            acc[q] = bv;
            acc[2 + q] = bv;
        }
        #pragma unroll
        for (int k4 = 0; k4 < 16; k4++) {
            float4 v0 = *reinterpret_cast<const float4*>(sm + S_U + p * 68 + k4 * 4);
            float4 v1 = *reinterpret_cast<const float4*>(sm + S_U + (p + 32) * 68 + k4 * 4);
            float a0[4] = {v0.x, v0.y, v0.z, v0.w};
            float a1[4] = {v1.x, v1.y, v1.z, v1.w};
            #pragma unroll
            for (int kk = 0; kk < 4; kk++) {
                const ulonglong2* wp = reinterpret_cast<const ulonglong2*>(
                    sm + S_WU2 + (k4 * 4 + kk) * 32 + c0);
                ulonglong2 w = wp[0];
                uint64_t x0 = dup2(a0[kk]);
                uint64_t x1 = dup2(a1[kk]);
                fma2(acc[0], x0, w.x);
                fma2(acc[1], x0, w.y);
                fma2(acc[2], x1, w.x);
                fma2(acc[3], x1, w.y);
            }
        }
        const float rw = *rwp;
        const float cw = 1.f - rw;
        #pragma unroll
        for (int j = 0; j < 2; j++) {
            const int n = p + j * 32;
            float4 fv = *reinterpret_cast<const float4*>(sm + S_F + n * 36 + c0);
            F2 x0; x0.u = acc[j * 2 + 0];
            F2 x1; x1.u = acc[j * 2 + 1];
            float4 o;
            o.x = rw * x0.f.x + cw * fv.x;
            o.y = rw * x0.f.y + cw * fv.y;
            o.z = rw * x1.f.x + cw * fv.z;
            o.w = rw * x1.f.y + cw * fv.w;
            *reinterpret_cast<float4*>(Og + (size_t)b * 2048 + n * 32 + c0) = o;
        }
    }
}

extern "C" void kernel_launch(void* const* d_in, const int* in_sizes, int n_in,
                              void* d_out, int out_size) {
    const float* Fg  = (const float*)d_in[0];
    const float* Wm1 = (const float*)d_in[1];
    const float* bm1 = (const float*)d_in[2];
    const float* Wm2 = (const float*)d_in[3];
    const float* bm2 = (const float*)d_in[4];
    const float* Wu1 = (const float*)d_in[5];
    const float* bu1 = (const float*)d_in[6];
    const float* Wu2 = (const float*)d_in[7];
    const float* bu2 = (const float*)d_in[8];
    const float* rwp = (const float*)d_in[9];
    float* Og = (float*)d_out;

    const int B = in_sizes[0] / (NJ * DD);
    const int smem_bytes = S_TOTAL * sizeof(float);

    static bool attr_set = false;
    if (!attr_set) {
        cudaFuncSetAttribute(agn_kernel,
                             cudaFuncAttributeMaxDynamicSharedMemorySize, smem_bytes);
        attr_set = true;
    }

    agn_kernel<<<B, 256, smem_bytes>>>(Fg, Wm1, bm1, Wm2, bm2,
                                       Wu1, bu1, Wu2, bu2, rwp, Og);
}

// round 4
// speedup vs baseline: 1.7730x; 1.7730x over previous
#include <cuda_runtime.h>
#include <cstdint>

#define NJ 64
#define DD 32
#define HH 64

// Shared memory layout (float offsets)
#define S_WC   0                    // Wm1 rearranged [32][128] = 4096
#define S_WM2  (S_WC + 4096)        // [64][32] = 2048
#define S_WU1  (S_WM2 + 2048)       // [64][64] = 4096
#define S_WU2  (S_WU1 + 4096)       // [64][32] = 2048
#define S_B    (S_WU2 + 2048)       // bm1[0:64) bm2[64:96) bu1[96:160) bu2[160:192)
#define S_F    (S_B + 192)          // [64][36] = 2304
#define S_M    (S_F + 2304)         // [64][36] = 2304
#define S_G    (S_M + 2304)         // G[64][132]=8448 ; reused as H[128][68]=8704 ; then U[64][68]
#define S_TOTAL (S_G + 8704)        // 25792 floats = 103168 bytes

union F2 { uint64_t u; float2 f; };

__device__ __forceinline__ uint64_t ld2s(const float* p) {
    return *reinterpret_cast<const uint64_t*>(p);
}
__device__ __forceinline__ void fma2(uint64_t& d, uint64_t a, uint64_t b) {
    asm("fma.rn.f32x2 %0, %1, %2, %0;" : "+l"(d) : "l"(a), "l"(b));
}
__device__ __forceinline__ uint64_t dup2(float a) {
    uint64_t r; asm("mov.b64 %0, {%1, %1};" : "=l"(r) : "f"(a)); return r;
}
__device__ __forceinline__ void relu2(uint64_t& v) {
    F2 x; x.u = v;
    x.f.x = fmaxf(x.f.x, 0.f);
    x.f.y = fmaxf(x.f.y, 0.f);
    v = x.u;
}

extern __shared__ float sm[];

__global__ void __launch_bounds__(256, 2)
agn_kernel(const float* __restrict__ Fg,
           const float* __restrict__ Wm1, const float* __restrict__ bm1,
           const float* __restrict__ Wm2, const float* __restrict__ bm2,
           const float* __restrict__ Wu1, const float* __restrict__ bu1,
           const float* __restrict__ Wu2, const float* __restrict__ bu2,
           const float* __restrict__ rwp,
           float* __restrict__ Og)
{
    const int b = blockIdx.x;
    const int t = threadIdx.x;

    // ================= stage 0: stage weights / biases / features =================
    // Wc[32][128]: Wc[k][c] = Wm1[k][c] for c<64 ; Wm1[k+32][c-64] for c>=64
    #pragma unroll
    for (int i = 0; i < 16; i++) {
        int gi = t + i * 256;
        int kg = gi >> 6, h = gi & 63;
        sm[S_WC + (kg & 31) * 128 + (kg >> 5) * 64 + h] = Wm1[gi];
    }
    #pragma unroll
    for (int i = 0; i < 2; i++) {
        int g = t + i * 256;
        reinterpret_cast<float4*>(sm + S_WM2)[g] = reinterpret_cast<const float4*>(Wm2)[g];
    }
    #pragma unroll
    for (int i = 0; i < 4; i++) {
        int g = t + i * 256;
        reinterpret_cast<float4*>(sm + S_WU1)[g] = reinterpret_cast<const float4*>(Wu1)[g];
    }
    #pragma unroll
    for (int i = 0; i < 2; i++) {
        int g = t + i * 256;
        reinterpret_cast<float4*>(sm + S_WU2)[g] = reinterpret_cast<const float4*>(Wu2)[g];
    }
    if (t < 64)        sm[S_B + t] = bm1[t];
    else if (t < 96)   sm[S_B + t] = bm2[t - 64];
    else if (t < 160)  sm[S_B + t] = bu1[t - 96];
    else if (t < 192)  sm[S_B + t] = bu2[t - 160];

    const float4* Fb4 = reinterpret_cast<const float4*>(Fg + (size_t)b * (NJ * DD));
    #pragma unroll
    for (int i = 0; i < 2; i++) {
        int g = t + i * 256;              // float4 index, 512 total
        int n = g >> 3, d4 = g & 7;
        *reinterpret_cast<float4*>(sm + S_F + n * 36 + d4 * 4) = Fb4[g];
    }
    __syncthreads();

    // ================= Stage 1: G[64][128] = F @ Wc  (j=8 rows/thread) =================
    // c0 = (t&31)*4 (4 cols, 2 pairs); rows p+8m, p = t>>5 (warp-uniform -> broadcast acts)
    {
        const int c0 = (t & 31) * 4;
        const int p  = t >> 5;
        uint64_t acc[16];
        #pragma unroll
        for (int i = 0; i < 16; i++) acc[i] = 0;

        #pragma unroll
        for (int k4 = 0; k4 < 8; k4++) {
            float fa[8][4];
            #pragma unroll
            for (int m = 0; m < 8; m++) {
                float4 v = *reinterpret_cast<const float4*>(sm + S_F + (p + 8*m) * 36 + k4 * 4);
                fa[m][0] = v.x; fa[m][1] = v.y; fa[m][2] = v.z; fa[m][3] = v.w;
            }
            #pragma unroll
            for (int kk = 0; kk < 4; kk++) {
                ulonglong2 w = *reinterpret_cast<const ulonglong2*>(
                    sm + S_WC + (k4 * 4 + kk) * 128 + c0);
                #pragma unroll
                for (int m = 0; m < 8; m++) {
                    uint64_t a2 = dup2(fa[m][kk]);
                    fma2(acc[2*m + 0], a2, w.x);
                    fma2(acc[2*m + 1], a2, w.y);
                }
            }
        }
        #pragma unroll
        for (int m = 0; m < 8; m++) {
            ulonglong2 o; o.x = acc[2*m]; o.y = acc[2*m + 1];
            *reinterpret_cast<ulonglong2*>(sm + S_G + (p + 8*m) * 132 + c0) = o;
        }
    }
    __syncthreads();

    // ================= Stage 2a: h1[128][68] = relu(G1[dn]+G2[sn]+bm1), pad rows 126/127 = 0
    // 2 threads/edge: e = t>>1, half 32 cols each. hrow = e.
    {
        float4 h[8];
        const int e  = t >> 1;
        const int d0 = (t & 1) * 32;
        const bool active = (t < 252);
        int dn, sn;
        if (e < 63) { dn = e;      sn = e + 1; }
        else        { dn = e - 62; sn = e - 63; }
        if (active) {
            #pragma unroll
            for (int q = 0; q < 8; q++) {
                float4 g1 = *reinterpret_cast<const float4*>(sm + S_G + dn * 132 + d0 + q * 4);
                float4 g2 = *reinterpret_cast<const float4*>(sm + S_G + sn * 132 + 64 + d0 + q * 4);
                float4 bb = *reinterpret_cast<const float4*>(sm + S_B + d0 + q * 4);
                h[q].x = fmaxf(g1.x + g2.x + bb.x, 0.f);
                h[q].y = fmaxf(g1.y + g2.y + bb.y, 0.f);
                h[q].z = fmaxf(g1.z + g2.z + bb.z, 0.f);
                h[q].w = fmaxf(g1.w + g2.w + bb.w, 0.f);
            }
        }
        __syncthreads();   // all G reads done before H overlays G
        if (active) {
            #pragma unroll
            for (int q = 0; q < 8; q++)
                *reinterpret_cast<float4*>(sm + S_G + e * 68 + d0 + q * 4) = h[q];
        } else {
            const int r   = 126 + ((t - 252) >> 1);
            const int c0z = ((t - 252) & 1) * 32;
            float4 z = make_float4(0.f, 0.f, 0.f, 0.f);
            #pragma unroll
            for (int q = 0; q < 8; q++)
                *reinterpret_cast<float4*>(sm + S_G + r * 68 + c0z + q * 4) = z;
        }
    }
    __syncthreads();

    // ================= Stage 2b: msg[128][32] = relu(H @ Wm2 + bm2); scatter to M ======
    // 128 threads: c0 = (t&7)*4 ; rows p+16m, p = t>>3 in [0,16), j=8
    {
        uint64_t acc[16];
        const int c0 = (t & 7) * 4;
        const int p  = t >> 3;
        if (t < 128) {
            const uint64_t b0 = ld2s(sm + S_B + 64 + c0);
            const uint64_t b1 = ld2s(sm + S_B + 64 + c0 + 2);
            #pragma unroll
            for (int m = 0; m < 8; m++) { acc[2*m] = b0; acc[2*m + 1] = b1; }
            #pragma unroll
            for (int k4 = 0; k4 < 16; k4++) {
                float ha[8][4];
                #pragma unroll
                for (int m = 0; m < 8; m++) {
                    float4 v = *reinterpret_cast<const float4*>(sm + S_G + (p + 16*m) * 68 + k4 * 4);
                    ha[m][0] = v.x; ha[m][1] = v.y; ha[m][2] = v.z; ha[m][3] = v.w;
                }
                #pragma unroll
                for (int kk = 0; kk < 4; kk++) {
                    ulonglong2 w = *reinterpret_cast<const ulonglong2*>(
                        sm + S_WM2 + (k4 * 4 + kk) * 32 + c0);
                    #pragma unroll
                    for (int m = 0; m < 8; m++) {
                        uint64_t a2 = dup2(ha[m][kk]);
                        fma2(acc[2*m + 0], a2, w.x);
                        fma2(acc[2*m + 1], a2, w.y);
                    }
                }
            }
            #pragma unroll
            for (int i = 0; i < 16; i++) relu2(acc[i]);
            // phase A: forward edges (row < 63) store M[row]
            #pragma unroll
            for (int m = 0; m < 8; m++) {
                int r = p + 16 * m;
                if (r < 63) {
                    ulonglong2 o; o.x = acc[2*m]; o.y = acc[2*m + 1];
                    *reinterpret_cast<ulonglong2*>(sm + S_M + r * 36 + c0) = o;
                }
            }
        }
        __syncthreads();
        // phase B: backward edges (63 <= row < 126) accumulate into M[row-62];
        // row 125 is the sole writer of node 63 -> plain store.
        if (t < 128) {
            #pragma unroll
            for (int m = 0; m < 8; m++) {
                int r = p + 16 * m;
                if (r >= 63 && r < 126) {
                    float* mp = sm + S_M + (r - 62) * 36 + c0;
                    F2 x0; x0.u = acc[2*m];
                    F2 x1; x1.u = acc[2*m + 1];
                    if (r == 125) {
                        mp[0] = x0.f.x; mp[1] = x0.f.y; mp[2] = x1.f.x; mp[3] = x1.f.y;
                    } else {
                        mp[0] += x0.f.x; mp[1] += x0.f.y; mp[2] += x1.f.x; mp[3] += x1.f.y;
                    }
                }
            }
        }
        __syncthreads();
    }

    // ================= Stage 3: U[64][64] = relu([F|M] @ Wu1 + bu1), U over H ======
    // 128 threads: c0 = (t&15)*4 ; rows p+8m, p = t>>4 in [0,8), j=8
    if (t < 128) {
        uint64_t acc[16];
        const int c0 = (t & 15) * 4;
        const int p  = t >> 4;
        const uint64_t b0 = ld2s(sm + S_B + 96 + c0);
        const uint64_t b1 = ld2s(sm + S_B + 96 + c0 + 2);
        #pragma unroll
        for (int m = 0; m < 8; m++) { acc[2*m] = b0; acc[2*m + 1] = b1; }

        #pragma unroll
        for (int half = 0; half < 2; half++) {
            const float* A = sm + (half == 0 ? S_F : S_M);
            const int kb = half * 32;
            #pragma unroll
            for (int k4 = 0; k4 < 8; k4++) {
                float fa[8][4];
                #pragma unroll
                for (int m = 0; m < 8; m++) {
                    float4 v = *reinterpret_cast<const float4*>(A + (p + 8*m) * 36 + k4 * 4);
                    fa[m][0] = v.x; fa[m][1] = v.y; fa[m][2] = v.z; fa[m][3] = v.w;
                }
                #pragma unroll
                for (int kk = 0; kk < 4; kk++) {
                    ulonglong2 w = *reinterpret_cast<const ulonglong2*>(
                        sm + S_WU1 + (kb + k4 * 4 + kk) * 64 + c0);
                    #pragma unroll
                    for (int m = 0; m < 8; m++) {
                        uint64_t a2 = dup2(fa[m][kk]);
                        fma2(acc[2*m + 0], a2, w.x);
                        fma2(acc[2*m + 1], a2, w.y);
                    }
                }
            }
        }
        #pragma unroll
        for (int m = 0; m < 8; m++) {
            relu2(acc[2*m]); relu2(acc[2*m + 1]);
            ulonglong2 o; o.x = acc[2*m]; o.y = acc[2*m + 1];
            *reinterpret_cast<ulonglong2*>(sm + S_G + (p + 8*m) * 68 + c0) = o;
        }
    }
    __syncthreads();

    // ================= Stage 4: out = rw*(U @ Wu2 + bu2) + (1-rw)*F ======
    // 128 threads: c0 = (t&7)*4 ; rows p+16m, p = t>>3 in [0,16), j=4
    if (t < 128) {
        uint64_t acc[8];
        const int c0 = (t & 7) * 4;
        const int p  = t >> 3;
        const uint64_t b0 = ld2s(sm + S_B + 160 + c0);
        const uint64_t b1 = ld2s(sm + S_B + 160 + c0 + 2);
        #pragma unroll
        for (int m = 0; m < 4; m++) { acc[2*m] = b0; acc[2*m + 1] = b1; }

        #pragma unroll
        for (int k4 = 0; k4 < 16; k4++) {
            float ua[4][4];
            #pragma unroll
            for (int m = 0; m < 4; m++) {
                float4 v = *reinterpret_cast<const float4*>(sm + S_G + (p + 16*m) * 68 + k4 * 4);
                ua[m][0] = v.x; ua[m][1] = v.y; ua[m][2] = v.z; ua[m][3] = v.w;
            }
            #pragma unroll
            for (int kk = 0; kk < 4; kk++) {
                ulonglong2 w = *reinterpret_cast<const ulonglong2*>(
                    sm + S_WU2 + (k4 * 4 + kk) * 32 + c0);
                #pragma unroll
                for (int m = 0; m < 4; m++) {
                    uint64_t a2 = dup2(ua[m][kk]);
                    fma2(acc[2*m + 0], a2, w.x);
                    fma2(acc[2*m + 1], a2, w.y);
                }
            }
        }
        const float rw = *rwp;
        const float cw = 1.f - rw;
        #pragma unroll
        for (int m = 0; m < 4; m++) {
            const int r = p + 16 * m;
            float4 fv = *reinterpret_cast<const float4*>(sm + S_F + r * 36 + c0);
            F2 x0; x0.u = acc[2*m];
            F2 x1; x1.u = acc[2*m + 1];
            float4 o;
            o.x = rw * x0.f.x + cw * fv.x;
            o.y = rw * x0.f.y + cw * fv.y;
            o.z = rw * x1.f.x + cw * fv.z;
            o.w = rw * x1.f.y + cw * fv.w;
            *reinterpret_cast<float4*>(Og + (size_t)b * 2048 + r * 32 + c0) = o;
        }
    }
}

extern "C" void kernel_launch(void* const* d_in, const int* in_sizes, int n_in,
                              void* d_out, int out_size) {
    const float* Fg  = (const float*)d_in[0];
    const float* Wm1 = (const float*)d_in[1];
    const float* bm1 = (const float*)d_in[2];
    const float* Wm2 = (const float*)d_in[3];
    const float* bm2 = (const float*)d_in[4];
    const float* Wu1 = (const float*)d_in[5];
    const float* bu1 = (const float*)d_in[6];
    const float* Wu2 = (const float*)d_in[7];
    const float* bu2 = (const float*)d_in[8];
    const float* rwp = (const float*)d_in[9];
    float* Og = (float*)d_out;

    const int B = in_sizes[0] / (NJ * DD);
    const int smem_bytes = S_TOTAL * sizeof(float);   // 103168

    static bool attr_set = false;
    if (!attr_set) {
        cudaFuncSetAttribute(agn_kernel,
                             cudaFuncAttributeMaxDynamicSharedMemorySize, smem_bytes);
        attr_set = true;
    }

    agn_kernel<<<B, 256, smem_bytes>>>(Fg, Wm1, bm1, Wm2, bm2,
                                       Wu1, bu1, Wu2, bu2, rwp, Og);
}